// round 12
// baseline (speedup 1.0000x reference)
#include <cuda_runtime.h>
#include <math.h>
#include <stdint.h>

// Problem constants
#define BB 4
#define TT 2048
#define BT (BB*TT)     // 8192
#define FF 512
#define HS 4
#define CS0 31
#define CS1 61
#define HALF0 15
#define HALF1 30
#define TCH 8          // tokens per window block (window_k) — best measured

#define W_SZ (FF*FF)
#define W2_0_SZ (HS*CS0*FF)
#define W2_1_SZ (HS*CS1*FF)
#define OFF_W1_0 0
#define OFF_W1_1 (W_SZ)
#define OFF_W3_0 (2*W_SZ)
#define OFF_W3_1 (3*W_SZ)
#define OFF_WOUT (4*W_SZ)
#define OFF_W2_0 (5*W_SZ)
#define OFF_W2_1 (5*W_SZ + W2_0_SZ)
#define WTF_TOTAL (5*W_SZ + W2_0_SZ + W2_1_SZ)

typedef unsigned long long ull;

// Scratch (device globals: alloc-free rule)
__device__ float g_qtf[BT*FF];
__device__ float g_vtf[BT*FF];
__device__ float g_wtf[WTF_TOTAL];
__device__ float g_rq0[BT*FF];
__device__ float g_rq1[BT*FF];
__device__ float g_v0 [BT*FF];
__device__ float g_v1 [BT*FF];
__device__ float g_mix[BT*FF];
__device__ float g_attn0[BT*HS*CS0];   // raw logits, softmaxed in window_k
__device__ float g_attn1[BT*HS*CS1];

__device__ __forceinline__ unsigned f2tf(float x) {
    unsigned r;
    asm("cvt.rna.tf32.f32 %0, %1;" : "=r"(r) : "f"(x));
    return r;
}
__device__ __forceinline__ float f2tf_f(float x) {
    return __uint_as_float(f2tf(x));
}

__device__ __forceinline__ ull pk2(float lo, float hi) {
    ull r;
    asm("mov.b64 %0, {%1, %2};" : "=l"(r) : "f"(lo), "f"(hi));
    return r;
}
__device__ __forceinline__ void upk2(float& lo, float& hi, ull v) {
    asm("mov.b64 {%0, %1}, %2;" : "=f"(lo), "=f"(hi) : "l"(v));
}
__device__ __forceinline__ ull ffma2(ull a, ull b, ull c) {
    ull d;
    asm("fma.rn.f32x2 %0, %1, %2, %3;" : "=l"(d) : "l"(a), "l"(b), "l"(c));
    return d;
}

__device__ __forceinline__ void mma_tf32(float c[4], unsigned a0, unsigned a1,
                                         unsigned a2, unsigned a3,
                                         unsigned b0, unsigned b1) {
    asm volatile(
        "mma.sync.aligned.m16n8k8.row.col.f32.tf32.tf32.f32 "
        "{%0,%1,%2,%3}, {%4,%5,%6,%7}, {%8,%9}, {%0,%1,%2,%3};"
        : "+f"(c[0]), "+f"(c[1]), "+f"(c[2]), "+f"(c[3])
        : "r"(a0), "r"(a1), "r"(a2), "r"(a3), "r"(b0), "r"(b1));
}

__device__ __forceinline__ uint4 ldsm_x4(unsigned addr) {
    uint4 r;
    asm volatile("ldmatrix.sync.aligned.m8n8.x4.shared.b16 {%0,%1,%2,%3}, [%4];"
                 : "=r"(r.x), "=r"(r.y), "=r"(r.z), "=r"(r.w) : "r"(addr));
    return r;
}

__device__ __forceinline__ void cp16(float* dst_smem, const float* src, bool pred) {
    unsigned d = (unsigned)__cvta_generic_to_shared(dst_smem);
    int sz = pred ? 16 : 0;
    asm volatile("cp.async.cg.shared.global [%0], [%1], 16, %2;"
                 :: "r"(d), "l"(src), "r"(sz));
}
__device__ __forceinline__ void cp_commit() {
    asm volatile("cp.async.commit_group;");
}

// ---------------------------------------------------------------------------
// tf32 rna-rounding prepass (inputs + weights only; cheap)
// ---------------------------------------------------------------------------
struct RDesc { const float* s; float* d; int n4; };
struct RArgs { RDesc r[9]; };

__global__ void round_k(RArgs a)
{
    RDesc t = a.r[blockIdx.z];
    int stride = gridDim.x * blockDim.x;
    for (int i = blockIdx.x * blockDim.x + threadIdx.x; i < t.n4; i += stride) {
        float4 v = ((const float4*)t.s)[i];
        ((uint4*)t.d)[i] = make_uint4(f2tf(v.x), f2tf(v.y), f2tf(v.z), f2tf(v.w));
    }
}

// ---------------------------------------------------------------------------
// Batched tf32 GEMM: C[M,N] = act( A[M,K] @ B[N,K]^T ).
// Inputs already tf32-rounded (raw bits). cp.async 2-stage double buffer
// (smem 73.7KB -> 2 CTAs/SM, 16 warps/SM = 4 warps/SMSP).
// Block tile 128x128x32, 256 threads / 8 warps, warp tile 64x32.
// Fragments via ldmatrix.x4: per kk-step 6 LDSM + 16 MMA per warp.
// flags: bit0 = relu, bit1 = round output to tf32
// ---------------------------------------------------------------------------
struct GemmDesc { const float* A; const float* B; float* C; int N; int flags; };
struct GemmArgs { GemmDesc d[4]; };

#define BM 128
#define BN 128
#define BK 32
#define STR 36
#define A_STG (BM*STR)
#define B_STG (BN*STR)
#define GEMM_SMEM (2*(A_STG + B_STG)*4)   // 73728 bytes

__global__ __launch_bounds__(256, 2)
void gemm_mma(GemmArgs args, int K)
{
    GemmDesc g = args.d[blockIdx.z];
    const int bn = blockIdx.x * BN;
    if (bn >= g.N) return;
    const int bm = blockIdx.y * BM;

    extern __shared__ float sm[];
    float* As = sm;                  // 2 stages
    float* Bs = sm + 2 * A_STG;      // 2 stages

    const int tid  = threadIdx.x;
    const int lane = tid & 31;
    const int warp = tid >> 5;    // 0..7
    const int wm   = warp >> 2;   // 0..1 -> 64 rows each
    const int wn   = warp & 3;    // 0..3 -> 32 cols each
    const int gid  = lane >> 2;   // 0..7
    const int quad = lane & 3;    // 0..3

    const int NT = K / BK;

    auto load_stage = [&](int s, int k0) {
        float* a = As + s * A_STG;
#pragma unroll
        for (int i = 0; i < 4; i++) {
            int id = tid + i * 256;
            int r  = id >> 3;
            int c  = (id & 7) * 4;
            cp16(a + r * STR + c, g.A + (size_t)(bm + r) * K + k0 + c, true);
        }
        float* b = Bs + s * B_STG;
#pragma unroll
        for (int i = 0; i < 4; i++) {
            int id = tid + i * 256;
            int r  = id >> 3;
            int c  = (id & 7) * 4;
            bool ok = (bn + r) < g.N;
            const float* src = ok ? (g.B + (size_t)(bn + r) * K + k0 + c) : g.B;
            cp16(b + r * STR + c, src, ok);
        }
        cp_commit();
    };

    float acc[4][4][4];
#pragma unroll
    for (int mt = 0; mt < 4; mt++)
#pragma unroll
        for (int nt = 0; nt < 4; nt++)
#pragma unroll
            for (int i = 0; i < 4; i++) acc[mt][nt][i] = 0.f;

    load_stage(0, 0);

    // ldmatrix lane -> (tile, row) decomposition
    const unsigned As_u32 = (unsigned)__cvta_generic_to_shared(As);
    const unsigned Bs_u32 = (unsigned)__cvta_generic_to_shared(Bs);
    const int lg = lane >> 3;    // tile index 0..3
    const int lr = lane & 7;     // row within tile
    // A x4 tiles: t0=(r0-7,c0-3), t1=(r8-15,c0-3), t2=(r0-7,c4-7), t3=(r8-15,c4-7)
    const int a_row = wm * 64 + lr + ((lg & 1) << 3);
    const int a_col = (lg >> 1) << 2;
    // B x4 tiles (2 nt per LDSM): t0=(nt0,c0-3), t1=(nt0,c4-7), t2=(nt1,c0-3), t3=(nt1,c4-7)
    const int b_row = wn * 32 + lr + ((lg >> 1) << 3);
    const int b_col = (lg & 1) << 2;

    for (int kt = 0; kt < NT; kt++) {
        asm volatile("cp.async.wait_group 0;");   // stage kt ready
        __syncthreads();                          // all warps done with stage kt-1

        if (kt + 1 < NT)
            load_stage((kt + 1) & 1, (kt + 1) * BK);  // overlaps compute of kt

        const unsigned aS = As_u32 + (unsigned)((kt & 1) * A_STG) * 4u;
        const unsigned bS = Bs_u32 + (unsigned)((kt & 1) * B_STG) * 4u;
        unsigned a_addr[4], b_addr[2];
#pragma unroll
        for (int mt = 0; mt < 4; mt++)
            a_addr[mt] = aS + (unsigned)(((a_row + mt * 16) * STR + a_col) * 4);
#pragma unroll
        for (int np = 0; np < 2; np++)
            b_addr[np] = bS + (unsigned)(((b_row + np * 16) * STR + b_col) * 4);

#pragma unroll
        for (int kk = 0; kk < BK; kk += 8) {
            uint4 af[4], bf[2];
#pragma unroll
            for (int mt = 0; mt < 4; mt++)
                af[mt] = ldsm_x4(a_addr[mt] + kk * 4);
#pragma unroll
            for (int np = 0; np < 2; np++)
                bf[np] = ldsm_x4(b_addr[np] + kk * 4);
#pragma unroll
            for (int mt = 0; mt < 4; mt++)
#pragma unroll
                for (int nt = 0; nt < 4; nt++) {
                    unsigned b0 = (nt & 1) ? bf[nt >> 1].z : bf[nt >> 1].x;
                    unsigned b1 = (nt & 1) ? bf[nt >> 1].w : bf[nt >> 1].y;
                    mma_tf32(acc[mt][nt], af[mt].x, af[mt].y, af[mt].z, af[mt].w,
                             b0, b1);
                }
        }
    }

    const int relu = g.flags & 1;
    const int rnd  = g.flags & 2;
#pragma unroll
    for (int mt = 0; mt < 4; mt++) {
        int r0 = bm + wm * 64 + mt * 16 + gid;
#pragma unroll
        for (int nt = 0; nt < 4; nt++) {
            int c0 = bn + wn * 32 + nt * 8 + quad * 2;
            float v0 = acc[mt][nt][0], v1 = acc[mt][nt][1];
            float v2 = acc[mt][nt][2], v3 = acc[mt][nt][3];
            if (relu) {
                v0 = fmaxf(v0, 0.f); v1 = fmaxf(v1, 0.f);
                v2 = fmaxf(v2, 0.f); v3 = fmaxf(v3, 0.f);
            }
            if (rnd) {
                v0 = f2tf_f(v0); v1 = f2tf_f(v1);
                v2 = f2tf_f(v2); v3 = f2tf_f(v3);
            }
            if (c0 < g.N) {
                g.C[(size_t)r0 * g.N + c0]       = v0;
                g.C[(size_t)(r0 + 8) * g.N + c0] = v2;
            }
            if (c0 + 1 < g.N) {
                g.C[(size_t)r0 * g.N + c0 + 1]       = v1;
                g.C[(size_t)(r0 + 8) * g.N + c0 + 1] = v3;
            }
        }
    }
}

// ---------------------------------------------------------------------------
// Windowed attention apply + fused softmax + scale mix.  (R8 best config)
// TCH=8 tokens/block, 256 threads x 2 features (float2 loads, fma.rn.f32x2).
// ---------------------------------------------------------------------------
__global__ __launch_bounds__(256)
void window_k(const float* __restrict__ sw_in)
{
    __shared__ ull   sd0[TCH * HS * CS0];     // duplicated softmax coeffs
    __shared__ ull   sd1[TCH * HS * CS1];
    __shared__ float ssw[2];

    int t0g = blockIdx.x * TCH;
    int b   = t0g / TT;
    int t0  = t0g - b * TT;
    int tid = threadIdx.x;

    if (tid == 0) {
        float a = sw_in[0], c = sw_in[1];
        float mx = fmaxf(a, c);
        float ea = __expf(a - mx), ec = __expf(c - mx);
        float inv = 1.f / (ea + ec);
        ssw[0] = ea * inv;
        ssw[1] = ec * inv;
    }

    // fused softmax: warp-per-row, logits straight from global
    {
        int warp = tid >> 5;
        int lane = tid & 31;
#pragma unroll
        for (int scale = 0; scale < 2; scale++) {
            int cs = scale ? CS1 : CS0;
            const float* gb = scale ? (g_attn1 + (size_t)t0g * (HS * CS1))
                                    : (g_attn0 + (size_t)t0g * (HS * CS0));
            ull* db = scale ? sd1 : sd0;
            for (int r = warp; r < TCH * HS; r += 8) {
                const float* p = gb + r * cs;
                ull* d = db + r * cs;
                float v0 = (lane      < cs) ? p[lane]      : -INFINITY;
                float v1 = (lane + 32 < cs) ? p[lane + 32] : -INFINITY;
                float m = fmaxf(v0, v1);
#pragma unroll
                for (int o = 16; o > 0; o >>= 1)
                    m = fmaxf(m, __shfl_xor_sync(0xFFFFFFFFu, m, o));
                float e0 = (lane      < cs) ? __expf(v0 - m) : 0.f;
                float e1 = (lane + 32 < cs) ? __expf(v1 - m) : 0.f;
                float s = e0 + e1;
#pragma unroll
                for (int o = 16; o > 0; o >>= 1)
                    s += __shfl_xor_sync(0xFFFFFFFFu, s, o);
                float inv = 1.f / s;
                if (lane < cs) {
                    float x = e0 * inv;
                    d[lane] = pk2(x, x);
                }
                if (lane + 32 < cs) {
                    float x = e1 * inv;
                    d[lane + 32] = pk2(x, x);
                }
            }
        }
    }
    __syncthreads();

    int f2 = tid * 2;            // first of 2 features owned by this thread
    int h  = f2 >> 7;            // head (uniform per warp)
    const float* v0b = g_v0 + ((size_t)b * TT) * FF + f2;
    const float* v1b = g_v1 + ((size_t)b * TT) * FF + f2;
    const ull* c0d = sd0 + h * CS0;
    const ull* c1d = sd1 + h * CS1;

    ull acc0[TCH], acc1[TCH];
#pragma unroll
    for (int j = 0; j < TCH; j++) { acc0[j] = 0ULL; acc1[j] = 0ULL; }

#pragma unroll
    for (int r = 0; r < TCH - 1 + CS0; r++) {
        int tp = t0 + r - HALF0;
        float2 vv = make_float2(0.f, 0.f);
        if ((unsigned)tp < (unsigned)TT)
            vv = *(const float2*)(v0b + (size_t)tp * FF);
        ull v01 = pk2(vv.x, vv.y);
#pragma unroll
        for (int j = 0; j < TCH; j++) {
            int c = r - j;
            if (c >= 0 && c < CS0)       // compile-time after unroll
                acc0[j] = ffma2(c0d[j * (HS * CS0) + c], v01, acc0[j]);
        }
    }
#pragma unroll
    for (int r = 0; r < TCH - 1 + CS1; r++) {
        int tp = t0 + r - HALF1;
        float2 vv = make_float2(0.f, 0.f);
        if ((unsigned)tp < (unsigned)TT)
            vv = *(const float2*)(v1b + (size_t)tp * FF);
        ull v01 = pk2(vv.x, vv.y);
#pragma unroll
        for (int j = 0; j < TCH; j++) {
            int c = r - j;
            if (c >= 0 && c < CS1)       // compile-time after unroll
                acc1[j] = ffma2(c1d[j * (HS * CS1) + c], v01, acc1[j]);
        }
    }

    float s0 = ssw[0], s1 = ssw[1];
#pragma unroll
    for (int j = 0; j < TCH; j++) {
        float a0x, a0y, a1x, a1y;
        upk2(a0x, a0y, acc0[j]);
        upk2(a1x, a1y, acc1[j]);
        uint2 o = make_uint2(f2tf(s0 * a0x + s1 * a1x),
                             f2tf(s0 * a0y + s1 * a1y));
        *(uint2*)&g_mix[(size_t)(t0g + j) * FF + f2] = o;
    }
}

// ---------------------------------------------------------------------------
extern "C" void kernel_launch(void* const* d_in, const int* in_sizes, int n_in,
                              void* d_out, int out_size)
{
    const float* query = (const float*)d_in[0];
    // d_in[1] = key (unused by reference)
    const float* value = (const float*)d_in[2];
    const float* w1_0  = (const float*)d_in[3];
    const float* w1_1  = (const float*)d_in[4];
    const float* w2_0  = (const float*)d_in[5];
    const float* w2_1  = (const float*)d_in[6];
    const float* w3_0  = (const float*)d_in[7];
    const float* w3_1  = (const float*)d_in[8];
    const float* sw    = (const float*)d_in[9];
    const float* w_out = (const float*)d_in[10];
    float* out = (float*)d_out;

    float *qtf, *vtf, *wtf, *rq0, *rq1, *v0, *v1, *mix, *a0, *a1;
    cudaGetSymbolAddress((void**)&qtf, g_qtf);
    cudaGetSymbolAddress((void**)&vtf, g_vtf);
    cudaGetSymbolAddress((void**)&wtf, g_wtf);
    cudaGetSymbolAddress((void**)&rq0, g_rq0);
    cudaGetSymbolAddress((void**)&rq1, g_rq1);
    cudaGetSymbolAddress((void**)&v0,  g_v0);
    cudaGetSymbolAddress((void**)&v1,  g_v1);
    cudaGetSymbolAddress((void**)&mix, g_mix);
    cudaGetSymbolAddress((void**)&a0,  g_attn0);
    cudaGetSymbolAddress((void**)&a1,  g_attn1);

    static bool attr_done = false;
    if (!attr_done) {
        cudaFuncSetAttribute(gemm_mma, cudaFuncAttributeMaxDynamicSharedMemorySize,
                             GEMM_SMEM);
        attr_done = true;
    }

    // 1) tf32 rounding prepass (inputs + weights)
    RArgs ra;
    ra.r[0] = {query, qtf, BT * FF / 4};
    ra.r[1] = {value, vtf, BT * FF / 4};
    ra.r[2] = {w1_0, wtf + OFF_W1_0, W_SZ / 4};
    ra.r[3] = {w1_1, wtf + OFF_W1_1, W_SZ / 4};
    ra.r[4] = {w3_0, wtf + OFF_W3_0, W_SZ / 4};
    ra.r[5] = {w3_1, wtf + OFF_W3_1, W_SZ / 4};
    ra.r[6] = {w_out, wtf + OFF_WOUT, W_SZ / 4};
    ra.r[7] = {w2_0, wtf + OFF_W2_0, W2_0_SZ / 4};
    ra.r[8] = {w2_1, wtf + OFF_W2_1, W2_1_SZ / 4};
    round_k<<<dim3(192, 1, 9), 256>>>(ra);

    // 2) 4 big GEMMs: q=relu(query@w1^T) [rounded], v=value@w3^T [raw fp32 out]
    GemmArgs gb;
    gb.d[0] = {qtf, wtf + OFF_W1_0, rq0, FF, 1 | 2};
    gb.d[1] = {qtf, wtf + OFF_W1_1, rq1, FF, 1 | 2};
    gb.d[2] = {vtf, wtf + OFF_W3_0, v0,  FF, 0};
    gb.d[3] = {vtf, wtf + OFF_W3_1, v1,  FF, 0};
    gemm_mma<<<dim3(FF / BN, BT / BM, 4), 256, GEMM_SMEM>>>(gb, FF);

    // 3) logits GEMMs (raw logits; softmax fused into window_k)
    GemmArgs gl;
    gl.d[0] = {rq0, wtf + OFF_W2_0, a0, HS * CS0, 0};
    gl.d[1] = {rq1, wtf + OFF_W2_1, a1, HS * CS1, 0};
    gl.d[2] = gl.d[0]; gl.d[3] = gl.d[0];
    gemm_mma<<<dim3((HS * CS1 + BN - 1) / BN, BT / BM, 2), 256, GEMM_SMEM>>>(gl, FF);

    // 4) fused softmax + window apply + scale mixing (mix rounded to tf32)
    window_k<<<BT / TCH, 256>>>(sw);

    // 5) final projection
    GemmArgs gf;
    gf.d[0] = {mix, wtf + OFF_WOUT, out, FF, 0};
    gf.d[1] = gf.d[0]; gf.d[2] = gf.d[0]; gf.d[3] = gf.d[0];
    gemm_mma<<<dim3(FF / BN, BT / BM, 1), 256, GEMM_SMEM>>>(gf, FF);
}

// round 13
// speedup vs baseline: 1.0490x; 1.0490x over previous
#include <cuda_runtime.h>
#include <math.h>
#include <stdint.h>

// Problem constants
#define BB 4
#define TT 2048
#define BT (BB*TT)     // 8192
#define FF 512
#define HS 4
#define CS0 31
#define CS1 61
#define HALF0 15
#define HALF1 30
#define TCH 8          // tokens per window block (window_k) — best measured

#define W_SZ (FF*FF)
#define W2_0_SZ (HS*CS0*FF)
#define W2_1_SZ (HS*CS1*FF)
#define OFF_W1_0 0
#define OFF_W1_1 (W_SZ)
#define OFF_W3_0 (2*W_SZ)
#define OFF_W3_1 (3*W_SZ)
#define OFF_WOUT (4*W_SZ)
#define OFF_W2_0 (5*W_SZ)
#define OFF_W2_1 (5*W_SZ + W2_0_SZ)
#define WTF_TOTAL (5*W_SZ + W2_0_SZ + W2_1_SZ)

typedef unsigned long long ull;

// Scratch (device globals: alloc-free rule)
__device__ float g_wtf[WTF_TOTAL];
__device__ float g_rq0[BT*FF];
__device__ float g_rq1[BT*FF];
__device__ float g_v0 [BT*FF];
__device__ float g_v1 [BT*FF];
__device__ float g_mix[BT*FF];
__device__ float g_attn0[BT*HS*CS0];   // raw logits, softmaxed in window_k
__device__ float g_attn1[BT*HS*CS1];

__device__ __forceinline__ unsigned f2tf(float x) {
    unsigned r;
    asm("cvt.rna.tf32.f32 %0, %1;" : "=r"(r) : "f"(x));
    return r;
}
__device__ __forceinline__ float f2tf_f(float x) {
    return __uint_as_float(f2tf(x));
}
__device__ __forceinline__ unsigned f2tf_u(unsigned x) {
    return f2tf(__uint_as_float(x));
}

__device__ __forceinline__ ull pk2(float lo, float hi) {
    ull r;
    asm("mov.b64 %0, {%1, %2};" : "=l"(r) : "f"(lo), "f"(hi));
    return r;
}
__device__ __forceinline__ void upk2(float& lo, float& hi, ull v) {
    asm("mov.b64 {%0, %1}, %2;" : "=f"(lo), "=f"(hi) : "l"(v));
}
__device__ __forceinline__ ull ffma2(ull a, ull b, ull c) {
    ull d;
    asm("fma.rn.f32x2 %0, %1, %2, %3;" : "=l"(d) : "l"(a), "l"(b), "l"(c));
    return d;
}

__device__ __forceinline__ void mma_tf32(float c[4], unsigned a0, unsigned a1,
                                         unsigned a2, unsigned a3,
                                         unsigned b0, unsigned b1) {
    asm volatile(
        "mma.sync.aligned.m16n8k8.row.col.f32.tf32.tf32.f32 "
        "{%0,%1,%2,%3}, {%4,%5,%6,%7}, {%8,%9}, {%0,%1,%2,%3};"
        : "+f"(c[0]), "+f"(c[1]), "+f"(c[2]), "+f"(c[3])
        : "r"(a0), "r"(a1), "r"(a2), "r"(a3), "r"(b0), "r"(b1));
}

__device__ __forceinline__ uint4 ldsm_x4(unsigned addr) {
    uint4 r;
    asm volatile("ldmatrix.sync.aligned.m8n8.x4.shared.b16 {%0,%1,%2,%3}, [%4];"
                 : "=r"(r.x), "=r"(r.y), "=r"(r.z), "=r"(r.w) : "r"(addr));
    return r;
}

__device__ __forceinline__ void cp16(float* dst_smem, const float* src, bool pred) {
    unsigned d = (unsigned)__cvta_generic_to_shared(dst_smem);
    int sz = pred ? 16 : 0;
    asm volatile("cp.async.cg.shared.global [%0], [%1], 16, %2;"
                 :: "r"(d), "l"(src), "r"(sz));
}
__device__ __forceinline__ void cp_commit() {
    asm volatile("cp.async.commit_group;");
}

// ---------------------------------------------------------------------------
// tf32 rna-rounding prepass (weights only; ~1.8MB)
// ---------------------------------------------------------------------------
struct RDesc { const float* s; float* d; int n4; };
struct RArgs { RDesc r[7]; };

__global__ void round_k(RArgs a)
{
    RDesc t = a.r[blockIdx.z];
    int stride = gridDim.x * blockDim.x;
    for (int i = blockIdx.x * blockDim.x + threadIdx.x; i < t.n4; i += stride) {
        float4 v = ((const float4*)t.s)[i];
        ((uint4*)t.d)[i] = make_uint4(f2tf(v.x), f2tf(v.y), f2tf(v.z), f2tf(v.w));
    }
}

// ---------------------------------------------------------------------------
// Batched tf32 GEMM: C[M,N] = act( A[M,K] @ B[N,K]^T ).
// B pre-rounded to tf32; A raw fp32 if CVT_A (fragments cvt'd after LDSM,
// bit-identical to pre-rounding) else pre-rounded.
// cp.async 3-stage, block 128x128x32, 128 threads / 4 warps, warp 64x64,
// ldmatrix.x4 fragment loads (R11 best-measured config).
// flags: bit0 = relu, bit1 = round output to tf32
// ---------------------------------------------------------------------------
struct GemmDesc { const float* A; const float* B; float* C; int N; int flags; };
struct GemmArgs { GemmDesc d[4]; };

#define BM 128
#define BN 128
#define BK 32
#define STR 36
#define A_STG (BM*STR)
#define B_STG (BN*STR)
#define GEMM_SMEM (3*(A_STG + B_STG)*4)   // 110592 bytes

template<int CVT_A>
__global__ __launch_bounds__(128, 2)
void gemm_mma(GemmArgs args, int K)
{
    GemmDesc g = args.d[blockIdx.z];
    const int bn = blockIdx.x * BN;
    if (bn >= g.N) return;
    const int bm = blockIdx.y * BM;

    extern __shared__ float sm[];
    float* As = sm;
    float* Bs = sm + 3 * A_STG;

    const int tid  = threadIdx.x;
    const int lane = tid & 31;
    const int warp = tid >> 5;    // 0..3
    const int wm   = warp >> 1;   // 0..1 -> 64 rows each
    const int wn   = warp & 1;    // 0..1 -> 64 cols each
    const int gid  = lane >> 2;   // 0..7
    const int quad = lane & 3;    // 0..3

    const int NT = K / BK;

    auto load_stage = [&](int s, int k0) {
        float* a = As + s * A_STG;
#pragma unroll
        for (int i = 0; i < 8; i++) {
            int id = tid + i * 128;
            int r  = id >> 3;
            int c  = (id & 7) * 4;
            cp16(a + r * STR + c, g.A + (size_t)(bm + r) * K + k0 + c, true);
        }
        float* b = Bs + s * B_STG;
#pragma unroll
        for (int i = 0; i < 8; i++) {
            int id = tid + i * 128;
            int r  = id >> 3;
            int c  = (id & 7) * 4;
            bool ok = (bn + r) < g.N;
            const float* src = ok ? (g.B + (size_t)(bn + r) * K + k0 + c) : g.B;
            cp16(b + r * STR + c, src, ok);
        }
        cp_commit();
    };

    float acc[4][8][4];
#pragma unroll
    for (int mt = 0; mt < 4; mt++)
#pragma unroll
        for (int nt = 0; nt < 8; nt++)
#pragma unroll
            for (int i = 0; i < 4; i++) acc[mt][nt][i] = 0.f;

    load_stage(0, 0);
    load_stage(1, BK);

    // ldmatrix lane -> (tile, row) decomposition
    const unsigned As_u32 = (unsigned)__cvta_generic_to_shared(As);
    const unsigned Bs_u32 = (unsigned)__cvta_generic_to_shared(Bs);
    const int lg = lane >> 3;    // tile index 0..3
    const int lr = lane & 7;     // row within tile
    const int a_row = wm * 64 + lr + ((lg & 1) << 3);
    const int a_col = (lg >> 1) << 2;
    const int b_row = wn * 64 + lr + ((lg >> 1) << 3);
    const int b_col = (lg & 1) << 2;

    for (int kt = 0; kt < NT; kt++) {
        if (kt == NT - 1)
            asm volatile("cp.async.wait_group 0;");
        else
            asm volatile("cp.async.wait_group 1;");
        __syncthreads();

        if (kt + 2 < NT)
            load_stage((kt + 2) % 3, (kt + 2) * BK);

        const unsigned aS = As_u32 + (unsigned)((kt % 3) * A_STG) * 4u;
        const unsigned bS = Bs_u32 + (unsigned)((kt % 3) * B_STG) * 4u;
        unsigned a_addr[4], b_addr[4];
#pragma unroll
        for (int mt = 0; mt < 4; mt++)
            a_addr[mt] = aS + (unsigned)(((a_row + mt * 16) * STR + a_col) * 4);
#pragma unroll
        for (int np = 0; np < 4; np++)
            b_addr[np] = bS + (unsigned)(((b_row + np * 16) * STR + b_col) * 4);

#pragma unroll
        for (int kk = 0; kk < BK; kk += 8) {
            uint4 af[4], bf[4];
#pragma unroll
            for (int mt = 0; mt < 4; mt++) {
                af[mt] = ldsm_x4(a_addr[mt] + kk * 4);
                if (CVT_A) {
                    af[mt].x = f2tf_u(af[mt].x);
                    af[mt].y = f2tf_u(af[mt].y);
                    af[mt].z = f2tf_u(af[mt].z);
                    af[mt].w = f2tf_u(af[mt].w);
                }
            }
#pragma unroll
            for (int np = 0; np < 4; np++)
                bf[np] = ldsm_x4(b_addr[np] + kk * 4);
#pragma unroll
            for (int mt = 0; mt < 4; mt++)
#pragma unroll
                for (int nt = 0; nt < 8; nt++) {
                    unsigned b0 = (nt & 1) ? bf[nt >> 1].z : bf[nt >> 1].x;
                    unsigned b1 = (nt & 1) ? bf[nt >> 1].w : bf[nt >> 1].y;
                    mma_tf32(acc[mt][nt], af[mt].x, af[mt].y, af[mt].z, af[mt].w,
                             b0, b1);
                }
        }
        __syncthreads();
    }

    const int relu = g.flags & 1;
    const int rnd  = g.flags & 2;
#pragma unroll
    for (int mt = 0; mt < 4; mt++) {
        int r0 = bm + wm * 64 + mt * 16 + gid;
#pragma unroll
        for (int nt = 0; nt < 8; nt++) {
            int c0 = bn + wn * 64 + nt * 8 + quad * 2;
            float v0 = acc[mt][nt][0], v1 = acc[mt][nt][1];
            float v2 = acc[mt][nt][2], v3 = acc[mt][nt][3];
            if (relu) {
                v0 = fmaxf(v0, 0.f); v1 = fmaxf(v1, 0.f);
                v2 = fmaxf(v2, 0.f); v3 = fmaxf(v3, 0.f);
            }
            if (rnd) {
                v0 = f2tf_f(v0); v1 = f2tf_f(v1);
                v2 = f2tf_f(v2); v3 = f2tf_f(v3);
            }
            if (c0 < g.N) {
                g.C[(size_t)r0 * g.N + c0]       = v0;
                g.C[(size_t)(r0 + 8) * g.N + c0] = v2;
            }
            if (c0 + 1 < g.N) {
                g.C[(size_t)r0 * g.N + c0 + 1]       = v1;
                g.C[(size_t)(r0 + 8) * g.N + c0 + 1] = v3;
            }
        }
    }
}

// ---------------------------------------------------------------------------
// Windowed attention apply + fused softmax + scale mix.  (R8 best config)
// TCH=8 tokens/block, 256 threads x 2 features (float2 loads, fma.rn.f32x2).
// ---------------------------------------------------------------------------
__global__ __launch_bounds__(256)
void window_k(const float* __restrict__ sw_in)
{
    __shared__ ull   sd0[TCH * HS * CS0];     // duplicated softmax coeffs
    __shared__ ull   sd1[TCH * HS * CS1];
    __shared__ float ssw[2];

    int t0g = blockIdx.x * TCH;
    int b   = t0g / TT;
    int t0  = t0g - b * TT;
    int tid = threadIdx.x;

    if (tid == 0) {
        float a = sw_in[0], c = sw_in[1];
        float mx = fmaxf(a, c);
        float ea = __expf(a - mx), ec = __expf(c - mx);
        float inv = 1.f / (ea + ec);
        ssw[0] = ea * inv;
        ssw[1] = ec * inv;
    }

    // fused softmax: warp-per-row, logits straight from global
    {
        int warp = tid >> 5;
        int lane = tid & 31;
#pragma unroll
        for (int scale = 0; scale < 2; scale++) {
            int cs = scale ? CS1 : CS0;
            const float* gb = scale ? (g_attn1 + (size_t)t0g * (HS * CS1))
                                    : (g_attn0 + (size_t)t0g * (HS * CS0));
            ull* db = scale ? sd1 : sd0;
            for (int r = warp; r < TCH * HS; r += 8) {
                const float* p = gb + r * cs;
                ull* d = db + r * cs;
                float v0 = (lane      < cs) ? p[lane]      : -INFINITY;
                float v1 = (lane + 32 < cs) ? p[lane + 32] : -INFINITY;
                float m = fmaxf(v0, v1);
#pragma unroll
                for (int o = 16; o > 0; o >>= 1)
                    m = fmaxf(m, __shfl_xor_sync(0xFFFFFFFFu, m, o));
                float e0 = (lane      < cs) ? __expf(v0 - m) : 0.f;
                float e1 = (lane + 32 < cs) ? __expf(v1 - m) : 0.f;
                float s = e0 + e1;
#pragma unroll
                for (int o = 16; o > 0; o >>= 1)
                    s += __shfl_xor_sync(0xFFFFFFFFu, s, o);
                float inv = 1.f / s;
                if (lane < cs) {
                    float x = e0 * inv;
                    d[lane] = pk2(x, x);
                }
                if (lane + 32 < cs) {
                    float x = e1 * inv;
                    d[lane + 32] = pk2(x, x);
                }
            }
        }
    }
    __syncthreads();

    int f2 = tid * 2;            // first of 2 features owned by this thread
    int h  = f2 >> 7;            // head (uniform per warp)
    const float* v0b = g_v0 + ((size_t)b * TT) * FF + f2;
    const float* v1b = g_v1 + ((size_t)b * TT) * FF + f2;
    const ull* c0d = sd0 + h * CS0;
    const ull* c1d = sd1 + h * CS1;

    ull acc0[TCH], acc1[TCH];
#pragma unroll
    for (int j = 0; j < TCH; j++) { acc0[j] = 0ULL; acc1[j] = 0ULL; }

#pragma unroll
    for (int r = 0; r < TCH - 1 + CS0; r++) {
        int tp = t0 + r - HALF0;
        float2 vv = make_float2(0.f, 0.f);
        if ((unsigned)tp < (unsigned)TT)
            vv = *(const float2*)(v0b + (size_t)tp * FF);
        ull v01 = pk2(vv.x, vv.y);
#pragma unroll
        for (int j = 0; j < TCH; j++) {
            int c = r - j;
            if (c >= 0 && c < CS0)       // compile-time after unroll
                acc0[j] = ffma2(c0d[j * (HS * CS0) + c], v01, acc0[j]);
        }
    }
#pragma unroll
    for (int r = 0; r < TCH - 1 + CS1; r++) {
        int tp = t0 + r - HALF1;
        float2 vv = make_float2(0.f, 0.f);
        if ((unsigned)tp < (unsigned)TT)
            vv = *(const float2*)(v1b + (size_t)tp * FF);
        ull v01 = pk2(vv.x, vv.y);
#pragma unroll
        for (int j = 0; j < TCH; j++) {
            int c = r - j;
            if (c >= 0 && c < CS1)       // compile-time after unroll
                acc1[j] = ffma2(c1d[j * (HS * CS1) + c], v01, acc1[j]);
        }
    }

    float s0 = ssw[0], s1 = ssw[1];
#pragma unroll
    for (int j = 0; j < TCH; j++) {
        float a0x, a0y, a1x, a1y;
        upk2(a0x, a0y, acc0[j]);
        upk2(a1x, a1y, acc1[j]);
        uint2 o = make_uint2(f2tf(s0 * a0x + s1 * a1x),
                             f2tf(s0 * a0y + s1 * a1y));
        *(uint2*)&g_mix[(size_t)(t0g + j) * FF + f2] = o;
    }
}

// ---------------------------------------------------------------------------
extern "C" void kernel_launch(void* const* d_in, const int* in_sizes, int n_in,
                              void* d_out, int out_size)
{
    const float* query = (const float*)d_in[0];
    // d_in[1] = key (unused by reference)
    const float* value = (const float*)d_in[2];
    const float* w1_0  = (const float*)d_in[3];
    const float* w1_1  = (const float*)d_in[4];
    const float* w2_0  = (const float*)d_in[5];
    const float* w2_1  = (const float*)d_in[6];
    const float* w3_0  = (const float*)d_in[7];
    const float* w3_1  = (const float*)d_in[8];
    const float* sw    = (const float*)d_in[9];
    const float* w_out = (const float*)d_in[10];
    float* out = (float*)d_out;

    float *wtf, *rq0, *rq1, *v0, *v1, *mix, *a0, *a1;
    cudaGetSymbolAddress((void**)&wtf, g_wtf);
    cudaGetSymbolAddress((void**)&rq0, g_rq0);
    cudaGetSymbolAddress((void**)&rq1, g_rq1);
    cudaGetSymbolAddress((void**)&v0,  g_v0);
    cudaGetSymbolAddress((void**)&v1,  g_v1);
    cudaGetSymbolAddress((void**)&mix, g_mix);
    cudaGetSymbolAddress((void**)&a0,  g_attn0);
    cudaGetSymbolAddress((void**)&a1,  g_attn1);

    static bool attr_done = false;
    if (!attr_done) {
        cudaFuncSetAttribute(gemm_mma<0>, cudaFuncAttributeMaxDynamicSharedMemorySize,
                             GEMM_SMEM);
        cudaFuncSetAttribute(gemm_mma<1>, cudaFuncAttributeMaxDynamicSharedMemorySize,
                             GEMM_SMEM);
        attr_done = true;
    }

    // 1) tf32 rounding prepass (weights only, ~1.8MB)
    RArgs ra;
    ra.r[0] = {w1_0, wtf + OFF_W1_0, W_SZ / 4};
    ra.r[1] = {w1_1, wtf + OFF_W1_1, W_SZ / 4};
    ra.r[2] = {w3_0, wtf + OFF_W3_0, W_SZ / 4};
    ra.r[3] = {w3_1, wtf + OFF_W3_1, W_SZ / 4};
    ra.r[4] = {w_out, wtf + OFF_WOUT, W_SZ / 4};
    ra.r[5] = {w2_0, wtf + OFF_W2_0, W2_0_SZ / 4};
    ra.r[6] = {w2_1, wtf + OFF_W2_1, W2_1_SZ / 4};
    round_k<<<dim3(40, 1, 7), 256>>>(ra);

    // 2) 4 big GEMMs: A = raw query/value, fragments cvt'd in-loop
    GemmArgs gb;
    gb.d[0] = {query, wtf + OFF_W1_0, rq0, FF, 1 | 2};
    gb.d[1] = {query, wtf + OFF_W1_1, rq1, FF, 1 | 2};
    gb.d[2] = {value, wtf + OFF_W3_0, v0,  FF, 0};
    gb.d[3] = {value, wtf + OFF_W3_1, v1,  FF, 0};
    gemm_mma<1><<<dim3(FF / BN, BT / BM, 4), 128, GEMM_SMEM>>>(gb, FF);

    // 3) logits GEMMs (A = rq, already rounded; softmax fused into window_k)
    GemmArgs gl;
    gl.d[0] = {rq0, wtf + OFF_W2_0, a0, HS * CS0, 0};
    gl.d[1] = {rq1, wtf + OFF_W2_1, a1, HS * CS1, 0};
    gl.d[2] = gl.d[0]; gl.d[3] = gl.d[0];
    gemm_mma<0><<<dim3((HS * CS1 + BN - 1) / BN, BT / BM, 2), 128, GEMM_SMEM>>>(gl, FF);

    // 4) fused softmax + window apply + scale mixing (mix rounded to tf32)
    window_k<<<BT / TCH, 256>>>(sw);

    // 5) final projection (A = mix, already rounded)
    GemmArgs gf;
    gf.d[0] = {mix, wtf + OFF_WOUT, out, FF, 0};
    gf.d[1] = gf.d[0]; gf.d[2] = gf.d[0]; gf.d[3] = gf.d[0];
    gemm_mma<0><<<dim3(FF / BN, BT / BM, 1), 128, GEMM_SMEM>>>(gf, FF);
}

// round 14
// speedup vs baseline: 1.1385x; 1.0853x over previous
#include <cuda_runtime.h>
#include <math.h>
#include <stdint.h>

// Problem constants
#define BB 4
#define TT 2048
#define BT (BB*TT)     // 8192
#define FF 512
#define HS 4
#define CS0 31
#define CS1 61
#define HALF0 15
#define HALF1 30
#define TCH 8          // tokens per window block (window_k) — best measured

#define W_SZ (FF*FF)
#define W2_0_SZ (HS*CS0*FF)
#define W2_1_SZ (HS*CS1*FF)
#define OFF_W1_0 0
#define OFF_W1_1 (W_SZ)
#define OFF_W3_0 (2*W_SZ)
#define OFF_W3_1 (3*W_SZ)
#define OFF_WOUT (4*W_SZ)
#define OFF_W2_0 (5*W_SZ)
#define OFF_W2_1 (5*W_SZ + W2_0_SZ)
#define WTF_TOTAL (5*W_SZ + W2_0_SZ + W2_1_SZ)

typedef unsigned long long ull;

// Scratch (device globals: alloc-free rule)
__device__ float g_wtf[WTF_TOTAL];
__device__ float g_rq0[BT*FF];
__device__ float g_rq1[BT*FF];
__device__ float g_v0 [BT*FF];
__device__ float g_v1 [BT*FF];
__device__ float g_mix[BT*FF];
__device__ float g_attn0[BT*HS*CS0];   // raw logits, softmaxed in window_k
__device__ float g_attn1[BT*HS*CS1];

__device__ __forceinline__ unsigned f2tf(float x) {
    unsigned r;
    asm("cvt.rna.tf32.f32 %0, %1;" : "=r"(r) : "f"(x));
    return r;
}
__device__ __forceinline__ float f2tf_f(float x) {
    return __uint_as_float(f2tf(x));
}
__device__ __forceinline__ unsigned f2tf_u(unsigned x) {
    return f2tf(__uint_as_float(x));
}

__device__ __forceinline__ ull pk2(float lo, float hi) {
    ull r;
    asm("mov.b64 %0, {%1, %2};" : "=l"(r) : "f"(lo), "f"(hi));
    return r;
}
__device__ __forceinline__ void upk2(float& lo, float& hi, ull v) {
    asm("mov.b64 {%0, %1}, %2;" : "=f"(lo), "=f"(hi) : "l"(v));
}
__device__ __forceinline__ ull ffma2(ull a, ull b, ull c) {
    ull d;
    asm("fma.rn.f32x2 %0, %1, %2, %3;" : "=l"(d) : "l"(a), "l"(b), "l"(c));
    return d;
}

__device__ __forceinline__ void mma_tf32(float c[4], unsigned a0, unsigned a1,
                                         unsigned a2, unsigned a3,
                                         unsigned b0, unsigned b1) {
    asm volatile(
        "mma.sync.aligned.m16n8k8.row.col.f32.tf32.tf32.f32 "
        "{%0,%1,%2,%3}, {%4,%5,%6,%7}, {%8,%9}, {%0,%1,%2,%3};"
        : "+f"(c[0]), "+f"(c[1]), "+f"(c[2]), "+f"(c[3])
        : "r"(a0), "r"(a1), "r"(a2), "r"(a3), "r"(b0), "r"(b1));
}

__device__ __forceinline__ uint4 ldsm_x4(unsigned addr) {
    uint4 r;
    asm volatile("ldmatrix.sync.aligned.m8n8.x4.shared.b16 {%0,%1,%2,%3}, [%4];"
                 : "=r"(r.x), "=r"(r.y), "=r"(r.z), "=r"(r.w) : "r"(addr));
    return r;
}

__device__ __forceinline__ void cp16(float* dst_smem, const float* src, bool pred) {
    unsigned d = (unsigned)__cvta_generic_to_shared(dst_smem);
    int sz = pred ? 16 : 0;
    asm volatile("cp.async.cg.shared.global [%0], [%1], 16, %2;"
                 :: "r"(d), "l"(src), "r"(sz));
}
__device__ __forceinline__ void cp_commit() {
    asm volatile("cp.async.commit_group;");
}

// ---------------------------------------------------------------------------
// tf32 rna-rounding prepass (weights only; ~1.8MB)
// ---------------------------------------------------------------------------
struct RDesc { const float* s; float* d; int n4; };
struct RArgs { RDesc r[7]; };

__global__ void round_k(RArgs a)
{
    RDesc t = a.r[blockIdx.z];
    int stride = gridDim.x * blockDim.x;
    for (int i = blockIdx.x * blockDim.x + threadIdx.x; i < t.n4; i += stride) {
        float4 v = ((const float4*)t.s)[i];
        ((uint4*)t.d)[i] = make_uint4(f2tf(v.x), f2tf(v.y), f2tf(v.z), f2tf(v.w));
    }
}

// ---------------------------------------------------------------------------
// Batched tf32 GEMM: C[M,N] = act( A[M,K] @ B[N,K]^T ).
// B pre-rounded to tf32; A raw fp32 if CVT_A (fragments cvt'd after LDSM,
// bit-identical to pre-rounding) else pre-rounded.
// cp.async 3-stage, block 128x128x32, 128 threads / 4 warps, warp 64x64,
// ldmatrix.x4 fragment loads.
// flags: bit0 = relu, bit1 = round output to tf32
// ---------------------------------------------------------------------------
struct GemmDesc { const float* A; const float* B; float* C; int N; int flags; };
struct GemmArgs { GemmDesc d[4]; };

#define BM 128
#define BN 128
#define BK 32
#define STR 36
#define A_STG (BM*STR)
#define B_STG (BN*STR)
#define GEMM_SMEM (3*(A_STG + B_STG)*4)   // 110592 bytes

template<int CVT_A>
__global__ __launch_bounds__(128, 2)
void gemm_mma(GemmArgs args, int K)
{
    GemmDesc g = args.d[blockIdx.z];
    const int bn = blockIdx.x * BN;
    if (bn >= g.N) return;
    const int bm = blockIdx.y * BM;

    extern __shared__ float sm[];
    float* As = sm;
    float* Bs = sm + 3 * A_STG;

    const int tid  = threadIdx.x;
    const int lane = tid & 31;
    const int warp = tid >> 5;    // 0..3
    const int wm   = warp >> 1;   // 0..1 -> 64 rows each
    const int wn   = warp & 1;    // 0..1 -> 64 cols each
    const int gid  = lane >> 2;   // 0..7
    const int quad = lane & 3;    // 0..3

    const int NT = K / BK;

    auto load_stage = [&](int s, int k0) {
        float* a = As + s * A_STG;
#pragma unroll
        for (int i = 0; i < 8; i++) {
            int id = tid + i * 128;
            int r  = id >> 3;
            int c  = (id & 7) * 4;
            cp16(a + r * STR + c, g.A + (size_t)(bm + r) * K + k0 + c, true);
        }
        float* b = Bs + s * B_STG;
#pragma unroll
        for (int i = 0; i < 8; i++) {
            int id = tid + i * 128;
            int r  = id >> 3;
            int c  = (id & 7) * 4;
            bool ok = (bn + r) < g.N;
            const float* src = ok ? (g.B + (size_t)(bn + r) * K + k0 + c) : g.B;
            cp16(b + r * STR + c, src, ok);
        }
        cp_commit();
    };

    float acc[4][8][4];
#pragma unroll
    for (int mt = 0; mt < 4; mt++)
#pragma unroll
        for (int nt = 0; nt < 8; nt++)
#pragma unroll
            for (int i = 0; i < 4; i++) acc[mt][nt][i] = 0.f;

    load_stage(0, 0);
    load_stage(1, BK);

    // ldmatrix lane -> (tile, row) decomposition
    const unsigned As_u32 = (unsigned)__cvta_generic_to_shared(As);
    const unsigned Bs_u32 = (unsigned)__cvta_generic_to_shared(Bs);
    const int lg = lane >> 3;    // tile index 0..3
    const int lr = lane & 7;     // row within tile
    const int a_row = wm * 64 + lr + ((lg & 1) << 3);
    const int a_col = (lg >> 1) << 2;
    const int b_row = wn * 64 + lr + ((lg >> 1) << 3);
    const int b_col = (lg & 1) << 2;

    for (int kt = 0; kt < NT; kt++) {
        if (kt == NT - 1)
            asm volatile("cp.async.wait_group 0;");
        else
            asm volatile("cp.async.wait_group 1;");
        __syncthreads();

        if (kt + 2 < NT)
            load_stage((kt + 2) % 3, (kt + 2) * BK);

        const unsigned aS = As_u32 + (unsigned)((kt % 3) * A_STG) * 4u;
        const unsigned bS = Bs_u32 + (unsigned)((kt % 3) * B_STG) * 4u;
        unsigned a_addr[4], b_addr[4];
#pragma unroll
        for (int mt = 0; mt < 4; mt++)
            a_addr[mt] = aS + (unsigned)(((a_row + mt * 16) * STR + a_col) * 4);
#pragma unroll
        for (int np = 0; np < 4; np++)
            b_addr[np] = bS + (unsigned)(((b_row + np * 16) * STR + b_col) * 4);

#pragma unroll
        for (int kk = 0; kk < BK; kk += 8) {
            uint4 af[4], bf[4];
#pragma unroll
            for (int mt = 0; mt < 4; mt++) {
                af[mt] = ldsm_x4(a_addr[mt] + kk * 4);
                if (CVT_A) {
                    af[mt].x = f2tf_u(af[mt].x);
                    af[mt].y = f2tf_u(af[mt].y);
                    af[mt].z = f2tf_u(af[mt].z);
                    af[mt].w = f2tf_u(af[mt].w);
                }
            }
#pragma unroll
            for (int np = 0; np < 4; np++)
                bf[np] = ldsm_x4(b_addr[np] + kk * 4);
#pragma unroll
            for (int mt = 0; mt < 4; mt++)
#pragma unroll
                for (int nt = 0; nt < 8; nt++) {
                    unsigned b0 = (nt & 1) ? bf[nt >> 1].z : bf[nt >> 1].x;
                    unsigned b1 = (nt & 1) ? bf[nt >> 1].w : bf[nt >> 1].y;
                    mma_tf32(acc[mt][nt], af[mt].x, af[mt].y, af[mt].z, af[mt].w,
                             b0, b1);
                }
        }
        __syncthreads();
    }

    const int relu = g.flags & 1;
    const int rnd  = g.flags & 2;
#pragma unroll
    for (int mt = 0; mt < 4; mt++) {
        int r0 = bm + wm * 64 + mt * 16 + gid;
#pragma unroll
        for (int nt = 0; nt < 8; nt++) {
            int c0 = bn + wn * 64 + nt * 8 + quad * 2;
            float v0 = acc[mt][nt][0], v1 = acc[mt][nt][1];
            float v2 = acc[mt][nt][2], v3 = acc[mt][nt][3];
            if (relu) {
                v0 = fmaxf(v0, 0.f); v1 = fmaxf(v1, 0.f);
                v2 = fmaxf(v2, 0.f); v3 = fmaxf(v3, 0.f);
            }
            if (rnd) {
                v0 = f2tf_f(v0); v1 = f2tf_f(v1);
                v2 = f2tf_f(v2); v3 = f2tf_f(v3);
            }
            if (c0 < g.N) {
                g.C[(size_t)r0 * g.N + c0]       = v0;
                g.C[(size_t)(r0 + 8) * g.N + c0] = v2;
            }
            if (c0 + 1 < g.N) {
                g.C[(size_t)r0 * g.N + c0 + 1]       = v1;
                g.C[(size_t)(r0 + 8) * g.N + c0 + 1] = v3;
            }
        }
    }
}

// ---------------------------------------------------------------------------
// Windowed attention apply + fused softmax + scale mix.  (R8 best config)
// TCH=8 tokens/block, 256 threads x 2 features (float2 loads, fma.rn.f32x2).
// ---------------------------------------------------------------------------
__global__ __launch_bounds__(256)
void window_k(const float* __restrict__ sw_in)
{
    __shared__ ull   sd0[TCH * HS * CS0];     // duplicated softmax coeffs
    __shared__ ull   sd1[TCH * HS * CS1];
    __shared__ float ssw[2];

    int t0g = blockIdx.x * TCH;
    int b   = t0g / TT;
    int t0  = t0g - b * TT;
    int tid = threadIdx.x;

    if (tid == 0) {
        float a = sw_in[0], c = sw_in[1];
        float mx = fmaxf(a, c);
        float ea = __expf(a - mx), ec = __expf(c - mx);
        float inv = 1.f / (ea + ec);
        ssw[0] = ea * inv;
        ssw[1] = ec * inv;
    }

    // fused softmax: warp-per-row, logits straight from global
    {
        int warp = tid >> 5;
        int lane = tid & 31;
#pragma unroll
        for (int scale = 0; scale < 2; scale++) {
            int cs = scale ? CS1 : CS0;
            const float* gb = scale ? (g_attn1 + (size_t)t0g * (HS * CS1))
                                    : (g_attn0 + (size_t)t0g * (HS * CS0));
            ull* db = scale ? sd1 : sd0;
            for (int r = warp; r < TCH * HS; r += 8) {
                const float* p = gb + r * cs;
                ull* d = db + r * cs;
                float v0 = (lane      < cs) ? p[lane]      : -INFINITY;
                float v1 = (lane + 32 < cs) ? p[lane + 32] : -INFINITY;
                float m = fmaxf(v0, v1);
#pragma unroll
                for (int o = 16; o > 0; o >>= 1)
                    m = fmaxf(m, __shfl_xor_sync(0xFFFFFFFFu, m, o));
                float e0 = (lane      < cs) ? __expf(v0 - m) : 0.f;
                float e1 = (lane + 32 < cs) ? __expf(v1 - m) : 0.f;
                float s = e0 + e1;
#pragma unroll
                for (int o = 16; o > 0; o >>= 1)
                    s += __shfl_xor_sync(0xFFFFFFFFu, s, o);
                float inv = 1.f / s;
                if (lane < cs) {
                    float x = e0 * inv;
                    d[lane] = pk2(x, x);
                }
                if (lane + 32 < cs) {
                    float x = e1 * inv;
                    d[lane + 32] = pk2(x, x);
                }
            }
        }
    }
    __syncthreads();

    int f2 = tid * 2;            // first of 2 features owned by this thread
    int h  = f2 >> 7;            // head (uniform per warp)
    const float* v0b = g_v0 + ((size_t)b * TT) * FF + f2;
    const float* v1b = g_v1 + ((size_t)b * TT) * FF + f2;
    const ull* c0d = sd0 + h * CS0;
    const ull* c1d = sd1 + h * CS1;

    ull acc0[TCH], acc1[TCH];
#pragma unroll
    for (int j = 0; j < TCH; j++) { acc0[j] = 0ULL; acc1[j] = 0ULL; }

#pragma unroll
    for (int r = 0; r < TCH - 1 + CS0; r++) {
        int tp = t0 + r - HALF0;
        float2 vv = make_float2(0.f, 0.f);
        if ((unsigned)tp < (unsigned)TT)
            vv = *(const float2*)(v0b + (size_t)tp * FF);
        ull v01 = pk2(vv.x, vv.y);
#pragma unroll
        for (int j = 0; j < TCH; j++) {
            int c = r - j;
            if (c >= 0 && c < CS0)       // compile-time after unroll
                acc0[j] = ffma2(c0d[j * (HS * CS0) + c], v01, acc0[j]);
        }
    }
#pragma unroll
    for (int r = 0; r < TCH - 1 + CS1; r++) {
        int tp = t0 + r - HALF1;
        float2 vv = make_float2(0.f, 0.f);
        if ((unsigned)tp < (unsigned)TT)
            vv = *(const float2*)(v1b + (size_t)tp * FF);
        ull v01 = pk2(vv.x, vv.y);
#pragma unroll
        for (int j = 0; j < TCH; j++) {
            int c = r - j;
            if (c >= 0 && c < CS1)       // compile-time after unroll
                acc1[j] = ffma2(c1d[j * (HS * CS1) + c], v01, acc1[j]);
        }
    }

    float s0 = ssw[0], s1 = ssw[1];
#pragma unroll
    for (int j = 0; j < TCH; j++) {
        float a0x, a0y, a1x, a1y;
        upk2(a0x, a0y, acc0[j]);
        upk2(a1x, a1y, acc1[j]);
        uint2 o = make_uint2(f2tf(s0 * a0x + s1 * a1x),
                             f2tf(s0 * a0y + s1 * a1y));
        *(uint2*)&g_mix[(size_t)(t0g + j) * FF + f2] = o;
    }
}

// ---------------------------------------------------------------------------
extern "C" void kernel_launch(void* const* d_in, const int* in_sizes, int n_in,
                              void* d_out, int out_size)
{
    const float* query = (const float*)d_in[0];
    // d_in[1] = key (unused by reference)
    const float* value = (const float*)d_in[2];
    const float* w1_0  = (const float*)d_in[3];
    const float* w1_1  = (const float*)d_in[4];
    const float* w2_0  = (const float*)d_in[5];
    const float* w2_1  = (const float*)d_in[6];
    const float* w3_0  = (const float*)d_in[7];
    const float* w3_1  = (const float*)d_in[8];
    const float* sw    = (const float*)d_in[9];
    const float* w_out = (const float*)d_in[10];
    float* out = (float*)d_out;

    float *wtf, *rq0, *rq1, *v0, *v1, *mix, *a0, *a1;
    cudaGetSymbolAddress((void**)&wtf, g_wtf);
    cudaGetSymbolAddress((void**)&rq0, g_rq0);
    cudaGetSymbolAddress((void**)&rq1, g_rq1);
    cudaGetSymbolAddress((void**)&v0,  g_v0);
    cudaGetSymbolAddress((void**)&v1,  g_v1);
    cudaGetSymbolAddress((void**)&mix, g_mix);
    cudaGetSymbolAddress((void**)&a0,  g_attn0);
    cudaGetSymbolAddress((void**)&a1,  g_attn1);

    static bool init_done = false;
    static cudaStream_t s2;
    static cudaEvent_t e0, e2;
    if (!init_done) {
        cudaFuncSetAttribute(gemm_mma<0>, cudaFuncAttributeMaxDynamicSharedMemorySize,
                             GEMM_SMEM);
        cudaFuncSetAttribute(gemm_mma<1>, cudaFuncAttributeMaxDynamicSharedMemorySize,
                             GEMM_SMEM);
        cudaStreamCreateWithFlags(&s2, cudaStreamNonBlocking);
        cudaEventCreateWithFlags(&e0, cudaEventDisableTiming);
        cudaEventCreateWithFlags(&e2, cudaEventDisableTiming);
        init_done = true;
    }

    // 1) tf32 rounding prepass (weights only, ~1.8MB)   [default stream]
    RArgs ra;
    ra.r[0] = {w1_0, wtf + OFF_W1_0, W_SZ / 4};
    ra.r[1] = {w1_1, wtf + OFF_W1_1, W_SZ / 4};
    ra.r[2] = {w3_0, wtf + OFF_W3_0, W_SZ / 4};
    ra.r[3] = {w3_1, wtf + OFF_W3_1, W_SZ / 4};
    ra.r[4] = {w_out, wtf + OFF_WOUT, W_SZ / 4};
    ra.r[5] = {w2_0, wtf + OFF_W2_0, W2_0_SZ / 4};
    ra.r[6] = {w2_1, wtf + OFF_W2_1, W2_1_SZ / 4};
    round_k<<<dim3(40, 1, 7), 256>>>(ra);
    cudaEventRecord(e0, 0);
    cudaStreamWaitEvent(s2, e0, 0);

    // 2a) q GEMMs on default stream: rq = relu(query@w1^T) [tf32-rounded out]
    GemmArgs gq;
    gq.d[0] = {query, wtf + OFF_W1_0, rq0, FF, 1 | 2};
    gq.d[1] = {query, wtf + OFF_W1_1, rq1, FF, 1 | 2};
    gq.d[2] = gq.d[0]; gq.d[3] = gq.d[0];
    gemm_mma<1><<<dim3(FF / BN, BT / BM, 2), 128, GEMM_SMEM>>>(gq, FF);

    // 2b) v GEMMs on s2 (concurrent with q GEMMs + logits): v = value@w3^T
    GemmArgs gv;
    gv.d[0] = {value, wtf + OFF_W3_0, v0, FF, 0};
    gv.d[1] = {value, wtf + OFF_W3_1, v1, FF, 0};
    gv.d[2] = gv.d[0]; gv.d[3] = gv.d[0];
    gemm_mma<1><<<dim3(FF / BN, BT / BM, 2), 128, GEMM_SMEM, s2>>>(gv, FF);
    cudaEventRecord(e2, s2);

    // 3) logits GEMMs on default (depends only on rq)
    GemmArgs gl;
    gl.d[0] = {rq0, wtf + OFF_W2_0, a0, HS * CS0, 0};
    gl.d[1] = {rq1, wtf + OFF_W2_1, a1, HS * CS1, 0};
    gl.d[2] = gl.d[0]; gl.d[3] = gl.d[0];
    gemm_mma<0><<<dim3((HS * CS1 + BN - 1) / BN, BT / BM, 2), 128, GEMM_SMEM>>>(gl, FF);

    // join: window needs v0/v1 from s2
    cudaStreamWaitEvent(0, e2, 0);

    // 4) fused softmax + window apply + scale mixing (mix rounded to tf32)
    window_k<<<BT / TCH, 256>>>(sw);

    // 5) final projection (A = mix, already rounded)
    GemmArgs gf;
    gf.d[0] = {mix, wtf + OFF_WOUT, out, FF, 0};
    gf.d[1] = gf.d[0]; gf.d[2] = gf.d[0]; gf.d[3] = gf.d[0];
    gemm_mma<0><<<dim3(FF / BN, BT / BM, 1), 128, GEMM_SMEM>>>(gf, FF);
}